// round 12
// baseline (speedup 1.0000x reference)
#include <cuda_runtime.h>

#define NCHAN  3
#define H      512
#define W      512
#define KS     21
#define KTAPS  (KS * KS)          // 441

// CTA tile: 64 output cols x 64 output rows, 128 threads = 4 warps.
// thread = (colg, py): colg 0..3 -> 16 cols; py 0..31 -> output rows Yb+2py, +2py+1.
// Input window: rows Yb-10..Yb+73 (84), cols Xb-12..Xb+75 (88 floats, 44 pairs).
#define TROWS  84
#define TPAIRS 48                 // 44 pairs padded for XOR-16 swizzle
#define PLANE  (TROWS * TPAIRS)

typedef unsigned long long ull;

// Zero-padded per-batch tap table in constant memory:
// ckpad[b][s][dx], s = dy+1 (s=0 and s=22 are zero rows). 32*23*21 floats = 61.8KB.
__constant__ float ckpad[32 * 23 * 21];
__device__   float g_kpad[32 * 23 * 21];   // staging (device-writable)

__device__ __forceinline__ void ffma2(ull& d, ull a, ull b) {
    asm("fma.rn.f32x2 %0, %1, %2, %0;" : "+l"(d) : "l"(a), "l"(b));
}
__device__ __forceinline__ ull pk(float lo, float hi) {
    ull r; asm("mov.b64 %0, {%1, %2};" : "=l"(r) : "f"(lo), "f"(hi)); return r;
}
__device__ __forceinline__ ull dup(float v) {
    ull r; asm("mov.b64 %0, {%1, %1};" : "=l"(r) : "f"(v)); return r;
}
__device__ __forceinline__ void unpk(ull v, float& lo, float& hi) {
    asm("mov.b64 {%0, %1}, %2;" : "=f"(lo), "=f"(hi) : "l"(v));
}

// ---- prep: build zero-padded tap table in device global --------------------
__global__ void prep_kernel(const float* __restrict__ k) {
    int i = blockIdx.x * 256 + threadIdx.x;
    if (i >= 32 * 23 * 21) return;
    int dx = i % 21;
    int s  = (i / 21) % 23;
    int b  = i / (21 * 23);
    float v = 0.f;
    if (s >= 1 && s <= 21) v = k[((size_t)b * 21 + (s - 1)) * 21 + dx];
    g_kpad[i] = v;
}

// dynamic smem: two swizzled pair-planes only (taps come from constant memory)
#define SMEM_BYTES (2 * PLANE * 8)

__global__ __launch_bounds__(128, 3) void conv_kernel(const float* __restrict__ x,
                                                      float* __restrict__ d_out) {
    extern __shared__ __align__(16) ull sm[];
    ull* smA = sm;
    ull* smB = sm + PLANE;

    const int tid = threadIdx.x;
    const int img = blockIdx.z;
    const int Xb  = blockIdx.x * 64;
    const int Yb  = blockIdx.y * 64;

    // ---- load window into dual per-slot-swizzled planes --------------------
    // A pair p: cols (Xb-12+2p, +1); B pair p: cols (Xb-12+2p+1, +2).
    // slot of pair p in row `row` = p ^ ((row>>1)&15); half-swap for 16B stores.
    const float* ximg = x + (size_t)img * H * W;
    for (int i = tid; i < TROWS * 22; i += 128) {
        int row = i / 22;
        int q   = i % 22;
        int gy  = Yb - 10 + row;
        int gx  = Xb - 12 + 4 * q;
        bool rok = ((unsigned)gy < H);
        float4 v = make_float4(0.f, 0.f, 0.f, 0.f);
        if (rok && gx >= 0 && gx <= W - 4)
            v = *reinterpret_cast<const float4*>(ximg + (size_t)gy * W + gx);
        float e4 = 0.f;
        int gx4 = gx + 4;
        if (rok && gx4 >= 0 && gx4 < W)
            e4 = ximg[(size_t)gy * W + gx4];

        int sw   = (row >> 1) & 15;
        int base = (2 * q) ^ (sw & 14);
        ull alo = pk(v.x, v.y), ahi = pk(v.z, v.w);
        ull blo = pk(v.y, v.z), bhi = pk(v.w, e4);
        if (sw & 1) { ull t = alo; alo = ahi; ahi = t; t = blo; blo = bhi; bhi = t; }
        ull* arow = smA + row * TPAIRS;
        ull* brow = smB + row * TPAIRS;
        *reinterpret_cast<ulonglong2*>(arow + base) = make_ulonglong2(alo, ahi);
        *reinterpret_cast<ulonglong2*>(brow + base) = make_ulonglong2(blo, bhi);
    }
    __syncthreads();

    // ---- main loop: 16 cols (8 column-pairs) x 2 rows per thread ------------
    // acc0[i] = (out[y0][X+2i], out[y0][X+2i+1]), acc1[i] = same for y1=y0+1.
    // Input row r (0..21) serves both: out0 with tap row dy=r (slot r+1),
    // out1 with dy=r-1 (slot r). Taps are warp-uniform constant loads.
    const int colg = tid >> 5;
    const int py   = tid & 31;
    const int p0   = colg * 8;

    const float* ck = ckpad + (size_t)(img / NCHAN) * (23 * 21);

    ull acc0[8], acc1[8];
#pragma unroll
    for (int i = 0; i < 8; ++i) { acc0[i] = 0ull; acc1[i] = 0ull; }

#pragma unroll 1
    for (int r = 0; r < 22; ++r) {
        const int rowi = 2 * py + r;
        const int sw   = (rowi >> 1) & 15;
        const ull* Ar = smA + rowi * TPAIRS;
        const ull* Br = smB + rowi * TPAIRS;

        // data pairs for this input row (shared by both output rows):
        // even offsets o=-10..24 -> A pairs p0+1..p0+18
        // odd  offsets o=-9..23  -> B pairs p0+1..p0+17
        ull pe[19], po[18];
#pragma unroll
        for (int j = 1; j <= 18; ++j) pe[j] = Ar[(p0 + j) ^ sw];
#pragma unroll
        for (int j = 1; j <= 17; ++j) po[j] = Br[(p0 + j) ^ sw];

        const float* k1r = ck + r * 21;       // taps for out1 (dy=r-1; slot r)
        const float* k0r = k1r + 21;          // taps for out0 (dy=r;   slot r+1)

#pragma unroll
        for (int dx = 0; dx < 21; ++dx) {
            ull kk0 = dup(k0r[dx]);
            ull kk1 = dup(k1r[dx]);
#pragma unroll
            for (int i = 0; i < 8; ++i) {
                const int o = 2 * i + dx - 10;          // col offset of pair start
                ull a = (o & 1) ? po[(o + 11) >> 1] : pe[(o + 12) >> 1];
                ffma2(acc0[i], a, kk0);
                ffma2(acc1[i], a, kk1);
            }
        }
    }

    // ---- store: 2 rows x 16 contiguous cols ---------------------------------
    float r0[16], r1[16];
#pragma unroll
    for (int i = 0; i < 8; ++i) {
        unpk(acc0[i], r0[2 * i], r0[2 * i + 1]);
        unpk(acc1[i], r1[2 * i], r1[2 * i + 1]);
    }

    float* op = d_out + ((size_t)img * H + Yb + 2 * py) * W + Xb + colg * 16;
#pragma unroll
    for (int j = 0; j < 4; ++j) {
        reinterpret_cast<float4*>(op)[j] =
            make_float4(r0[4 * j], r0[4 * j + 1], r0[4 * j + 2], r0[4 * j + 3]);
        reinterpret_cast<float4*>(op + W)[j] =
            make_float4(r1[4 * j], r1[4 * j + 1], r1[4 * j + 2], r1[4 * j + 3]);
    }
}

extern "C" void kernel_launch(void* const* d_in, const int* in_sizes, int n_in,
                              void* d_out, int out_size) {
    const float* x = (const float*)d_in[0];   // (32,3,512,512) fp32
    const float* k = (const float*)d_in[1];   // (32,1,21,21)  fp32
    float* out = (float*)d_out;

    // 1) build padded tap table in device global, then copy into __constant__
    const int ktot = 32 * 23 * 21;
    prep_kernel<<<(ktot + 255) / 256, 256>>>(k);

    void* kpad_addr = nullptr;
    cudaGetSymbolAddress(&kpad_addr, g_kpad);
    cudaMemcpyToSymbolAsync(ckpad, kpad_addr, ktot * sizeof(float), 0,
                            cudaMemcpyDeviceToDevice, 0);

    // 2) main conv
    cudaFuncSetAttribute(conv_kernel,
                         cudaFuncAttributeMaxDynamicSharedMemorySize, SMEM_BYTES);
    dim3 grid(W / 64, H / 64, 96);            // (8, 8, 96)
    conv_kernel<<<grid, 128, SMEM_BYTES>>>(x, out);
}

// round 13
// speedup vs baseline: 1.0032x; 1.0032x over previous
#include <cuda_runtime.h>

#define NCHAN  3
#define H      512
#define W      512
#define KS     21
#define KTAPS  (KS * KS)          // 441

// CTA tile: 64 output cols x 64 output rows, 128 threads = 4 warps.
// thread = (colg, py): colg 0..3 -> 16 cols; py 0..31 -> output rows Yb+2py, +2py+1.
// Input window: rows Yb-10..Yb+73 (84), cols Xb-12..Xb+75 (88 floats, 44 pairs).
#define TROWS  84
#define TPAIRS 48                 // 44 pairs padded for XOR-16 swizzle
#define PLANE  (TROWS * TPAIRS)

typedef unsigned long long ull;

// Zero-padded per-batch tap table in constant memory:
// ckpad[b][s][dx], s = dy+1 (s=0 and s=22 are zero rows). 32*23*21 floats = 61.8KB.
__constant__ float ckpad[32 * 23 * 21];
__device__   float g_kpad[32 * 23 * 21];   // staging (device-writable)

__device__ __forceinline__ void ffma2(ull& d, ull a, ull b) {
    asm("fma.rn.f32x2 %0, %1, %2, %0;" : "+l"(d) : "l"(a), "l"(b));
}
__device__ __forceinline__ ull pk(float lo, float hi) {
    ull r; asm("mov.b64 %0, {%1, %2};" : "=l"(r) : "f"(lo), "f"(hi)); return r;
}
__device__ __forceinline__ ull dup(float v) {
    ull r; asm("mov.b64 %0, {%1, %1};" : "=l"(r) : "f"(v)); return r;
}
__device__ __forceinline__ void unpk(ull v, float& lo, float& hi) {
    asm("mov.b64 {%0, %1}, %2;" : "=f"(lo), "=f"(hi) : "l"(v));
}

// ---- prep: build zero-padded tap table in device global --------------------
__global__ void prep_kernel(const float* __restrict__ k) {
    int i = blockIdx.x * 256 + threadIdx.x;
    if (i >= 32 * 23 * 21) return;
    int dx = i % 21;
    int s  = (i / 21) % 23;
    int b  = i / (21 * 23);
    float v = 0.f;
    if (s >= 1 && s <= 21) v = k[((size_t)b * 21 + (s - 1)) * 21 + dx];
    g_kpad[i] = v;
}

// dynamic smem: two swizzled pair-planes only (taps come from constant memory)
#define SMEM_BYTES (2 * PLANE * 8)

__global__ __launch_bounds__(128, 3) void conv_kernel(const float* __restrict__ x,
                                                      float* __restrict__ d_out) {
    extern __shared__ __align__(16) ull sm[];
    ull* smA = sm;
    ull* smB = sm + PLANE;

    const int tid = threadIdx.x;
    const int img = blockIdx.z;
    const int Xb  = blockIdx.x * 64;
    const int Yb  = blockIdx.y * 64;

    // ---- load window into dual per-slot-swizzled planes --------------------
    // A pair p: cols (Xb-12+2p, +1); B pair p: cols (Xb-12+2p+1, +2).
    // slot of pair p in row `row` = p ^ ((row>>1)&15); half-swap for 16B stores.
    const float* ximg = x + (size_t)img * H * W;
    for (int i = tid; i < TROWS * 22; i += 128) {
        int row = i / 22;
        int q   = i % 22;
        int gy  = Yb - 10 + row;
        int gx  = Xb - 12 + 4 * q;
        bool rok = ((unsigned)gy < H);
        float4 v = make_float4(0.f, 0.f, 0.f, 0.f);
        if (rok && gx >= 0 && gx <= W - 4)
            v = *reinterpret_cast<const float4*>(ximg + (size_t)gy * W + gx);
        float e4 = 0.f;
        int gx4 = gx + 4;
        if (rok && gx4 >= 0 && gx4 < W)
            e4 = ximg[(size_t)gy * W + gx4];

        int sw   = (row >> 1) & 15;
        int base = (2 * q) ^ (sw & 14);
        ull alo = pk(v.x, v.y), ahi = pk(v.z, v.w);
        ull blo = pk(v.y, v.z), bhi = pk(v.w, e4);
        if (sw & 1) { ull t = alo; alo = ahi; ahi = t; t = blo; blo = bhi; bhi = t; }
        ull* arow = smA + row * TPAIRS;
        ull* brow = smB + row * TPAIRS;
        *reinterpret_cast<ulonglong2*>(arow + base) = make_ulonglong2(alo, ahi);
        *reinterpret_cast<ulonglong2*>(brow + base) = make_ulonglong2(blo, bhi);
    }
    __syncthreads();

    // ---- main loop: 16 cols (8 column-pairs) x 2 rows per thread ------------
    // acc0[i] = (out[y0][X+2i], out[y0][X+2i+1]), acc1[i] = same for y1=y0+1.
    // Input row r (0..21) serves both: out0 with tap row dy=r (slot r+1),
    // out1 with dy=r-1 (slot r). Taps are warp-uniform constant loads.
    const int colg = tid >> 5;
    const int py   = tid & 31;
    const int p0   = colg * 8;

    const float* ck = ckpad + (size_t)(img / NCHAN) * (23 * 21);

    ull acc0[8], acc1[8];
#pragma unroll
    for (int i = 0; i < 8; ++i) { acc0[i] = 0ull; acc1[i] = 0ull; }

#pragma unroll 1
    for (int r = 0; r < 22; ++r) {
        const int rowi = 2 * py + r;
        const int sw   = (rowi >> 1) & 15;
        const ull* Ar = smA + rowi * TPAIRS;
        const ull* Br = smB + rowi * TPAIRS;

        // data pairs for this input row (shared by both output rows):
        // even offsets o=-10..24 -> A pairs p0+1..p0+18
        // odd  offsets o=-9..23  -> B pairs p0+1..p0+17
        ull pe[19], po[18];
#pragma unroll
        for (int j = 1; j <= 18; ++j) pe[j] = Ar[(p0 + j) ^ sw];
#pragma unroll
        for (int j = 1; j <= 17; ++j) po[j] = Br[(p0 + j) ^ sw];

        const float* k1r = ck + r * 21;       // taps for out1 (dy=r-1; slot r)
        const float* k0r = k1r + 21;          // taps for out0 (dy=r;   slot r+1)

#pragma unroll
        for (int dx = 0; dx < 21; ++dx) {
            ull kk0 = dup(k0r[dx]);
            ull kk1 = dup(k1r[dx]);
#pragma unroll
            for (int i = 0; i < 8; ++i) {
                const int o = 2 * i + dx - 10;          // col offset of pair start
                ull a = (o & 1) ? po[(o + 11) >> 1] : pe[(o + 12) >> 1];
                ffma2(acc0[i], a, kk0);
                ffma2(acc1[i], a, kk1);
            }
        }
    }

    // ---- store: 2 rows x 16 contiguous cols ---------------------------------
    float r0[16], r1[16];
#pragma unroll
    for (int i = 0; i < 8; ++i) {
        unpk(acc0[i], r0[2 * i], r0[2 * i + 1]);
        unpk(acc1[i], r1[2 * i], r1[2 * i + 1]);
    }

    float* op = d_out + ((size_t)img * H + Yb + 2 * py) * W + Xb + colg * 16;
#pragma unroll
    for (int j = 0; j < 4; ++j) {
        reinterpret_cast<float4*>(op)[j] =
            make_float4(r0[4 * j], r0[4 * j + 1], r0[4 * j + 2], r0[4 * j + 3]);
        reinterpret_cast<float4*>(op + W)[j] =
            make_float4(r1[4 * j], r1[4 * j + 1], r1[4 * j + 2], r1[4 * j + 3]);
    }
}

extern "C" void kernel_launch(void* const* d_in, const int* in_sizes, int n_in,
                              void* d_out, int out_size) {
    const float* x = (const float*)d_in[0];   // (32,3,512,512) fp32
    const float* k = (const float*)d_in[1];   // (32,1,21,21)  fp32
    float* out = (float*)d_out;

    // 1) build padded tap table in device global, then copy into __constant__
    const int ktot = 32 * 23 * 21;
    prep_kernel<<<(ktot + 255) / 256, 256>>>(k);

    void* kpad_addr = nullptr;
    cudaGetSymbolAddress(&kpad_addr, g_kpad);
    cudaMemcpyToSymbolAsync(ckpad, kpad_addr, ktot * sizeof(float), 0,
                            cudaMemcpyDeviceToDevice, 0);

    // 2) main conv
    cudaFuncSetAttribute(conv_kernel,
                         cudaFuncAttributeMaxDynamicSharedMemorySize, SMEM_BYTES);
    dim3 grid(W / 64, H / 64, 96);            // (8, 8, 96)
    conv_kernel<<<grid, 128, SMEM_BYTES>>>(x, out);
}

// round 15
// speedup vs baseline: 1.6792x; 1.6738x over previous
#include <cuda_runtime.h>
#include <cuda_bf16.h>
#include <cstdint>

#define NCHAN 3
#define H 512
#define W 512

// CTA: 64 out rows x 64 out cols, 128 threads = 4 warps (warp w: rows w*16..+15).
// Window: input rows Yb-10..Yb+73 (84), cols Xb-12..Xb+75 (88 used, rows padded
// to 104 bf16 = 208B so ldmatrix's 8-row fetch hits 8 distinct 16B bank groups).
#define WR   84
#define WRB  208

#define OFF_H  0
#define OFF_L  (WR * WRB)            // 17472
#define OFF_BF (2 * WR * WRB)        // 34944: B frags [dy][split][khalf][lane] uint2
#define SMEM_TOTAL (OFF_BF + 21 * 2 * 2 * 32 * 8)   // 56448 B

typedef uint32_t u32;

__device__ __forceinline__ u32 s2u(const void* p) {
    u32 a;
    asm("{ .reg .u64 t; cvta.to.shared.u64 t, %1; cvt.u32.u64 %0, t; }"
        : "=r"(a) : "l"(p));
    return a;
}
__device__ __forceinline__ void mma16816(float* d, const u32* a, u32 b0, u32 b1) {
    asm volatile("mma.sync.aligned.m16n8k16.row.col.f32.bf16.bf16.f32 "
        "{%0,%1,%2,%3}, {%4,%5,%6,%7}, {%8,%9}, {%0,%1,%2,%3};"
        : "+f"(d[0]), "+f"(d[1]), "+f"(d[2]), "+f"(d[3])
        : "r"(a[0]), "r"(a[1]), "r"(a[2]), "r"(a[3]), "r"(b0), "r"(b1));
}
__device__ __forceinline__ void ldmx4(u32* g, u32 addr) {
    asm volatile("ldmatrix.sync.aligned.m8n8.x4.shared.b16 {%0,%1,%2,%3}, [%4];"
        : "=r"(g[0]), "=r"(g[1]), "=r"(g[2]), "=r"(g[3]) : "r"(addr));
}
__device__ __forceinline__ unsigned short bh(float v) {
    return __bfloat16_as_ushort(__float2bfloat16(v));
}
__device__ __forceinline__ float bhf(unsigned short u) {
    return __bfloat162float(__ushort_as_bfloat16(u));
}

__global__ __launch_bounds__(128) void conv_mma(const float* __restrict__ x,
                                                const float* __restrict__ dk,
                                                float* __restrict__ dout) {
    extern __shared__ __align__(16) char sm[];
    const u32 smb = s2u(sm);
    const int tid  = threadIdx.x;
    const int w    = tid >> 5;
    const int lane = tid & 31;
    const int img  = blockIdx.z;
    const int Xb   = blockIdx.x * 64;
    const int Yb   = blockIdx.y * 64;

    // ---- B fragments: B_dy[k][n] = tap_split[dy][k-n-2], band 2<=k-n<=22 ------
    // frag layout (m16n8k16 col-major B): lane: n = lane/4, k0 = (lane%4)*2+16*khalf
    // reg0 = {B[k0][n], B[k0+1][n]}, reg1 = {B[k0+8][n], B[k0+9][n]}
    const float* kp = dk + (size_t)(img / NCHAN) * 441;
    uint2* Bf = reinterpret_cast<uint2*>(sm + OFF_BF);
    for (int t = 0; t < 21; ++t) {
        int i = tid + (t << 7);          // 21*128 = 2688 entries
        int dy = i >> 7, r = i & 127;
        int split = (r >> 6) & 1, khalf = (r >> 5) & 1, l2 = r & 31;
        int n = l2 >> 2, k0 = (l2 & 3) * 2 + khalf * 16;
        unsigned short e[4];
#pragma unroll
        for (int q = 0; q < 4; ++q) {
            int k = k0 + (q & 1) + (q >> 1) * 8;
            int dx = k - n - 2;
            float tv = (dx >= 0 && dx <= 20) ? kp[dy * 21 + dx] : 0.f;
            if (split == 0) e[q] = bh(tv);
            else            e[q] = bh(tv - bhf(bh(tv)));
        }
        Bf[((dy * 2 + split) * 2 + khalf) * 32 + l2] =
            make_uint2((u32)e[0] | ((u32)e[1] << 16), (u32)e[2] | ((u32)e[3] << 16));
    }

    // ---- window load: fp32 -> bf16 hi/lo planes ------------------------------
    const float* ximg = x + (size_t)img * H * W;
    for (int i = tid; i < WR * 22; i += 128) {
        int row = i / 22, q = i % 22;
        int gy = Yb - 10 + row, gx = Xb - 12 + 4 * q;   // gx % 4 == 0: full in/out
        float4 v = make_float4(0.f, 0.f, 0.f, 0.f);
        if ((unsigned)gy < H && gx >= 0 && gx <= W - 4)
            v = *reinterpret_cast<const float4*>(ximg + (size_t)gy * W + gx);
        unsigned short h0 = bh(v.x), h1 = bh(v.y), h2 = bh(v.z), h3 = bh(v.w);
        unsigned short l0 = bh(v.x - bhf(h0)), l1 = bh(v.y - bhf(h1));
        unsigned short l2 = bh(v.z - bhf(h2)), l3 = bh(v.w - bhf(h3));
        u32 off = (u32)row * WRB + (u32)q * 8;
        *reinterpret_cast<uint2*>(sm + OFF_H + off) =
            make_uint2((u32)h0 | ((u32)h1 << 16), (u32)h2 | ((u32)h3 << 16));
        *reinterpret_cast<uint2*>(sm + OFF_L + off) =
            make_uint2((u32)l0 | ((u32)l1 << 16), (u32)l2 | ((u32)l3 << 16));
    }
    __syncthreads();

    // ---- main loop ------------------------------------------------------------
    // ldmatrix.x4 lane->row/col: lanes 0-15 rows rb+ (lane&15) col cb;
    // lanes 16-31 rows rb+(lane&15), col cb+8 (bytes +16).
    const u32 lrow = (u32)(lane & 15);
    const u32 lcol = (u32)(lane >> 4) * 16;

    float acc[8][4];
#pragma unroll
    for (int j = 0; j < 8; ++j)
#pragma unroll
        for (int q = 0; q < 4; ++q) acc[j][q] = 0.f;

    const uint2* Bfw = Bf;   // per-warp same data (broadcast)

#pragma unroll 1
    for (int dy = 0; dy < 21; ++dy) {
        const u32 rb = (u32)(w * 16 + dy);
        const u32 aH = smb + OFF_H + (rb + lrow) * WRB + lcol;
        const u32 aL = aH + (OFF_L - OFF_H);

        // B frags for this dy
        uint2 bk0 = Bfw[((dy * 2 + 0) * 2 + 0) * 32 + lane];
        uint2 bk1 = Bfw[((dy * 2 + 0) * 2 + 1) * 32 + lane];
        uint2 bl0 = Bfw[((dy * 2 + 1) * 2 + 0) * 32 + lane];
        uint2 bl1 = Bfw[((dy * 2 + 1) * 2 + 1) * 32 + lane];

        // A hi-plane frags G_t (16 rows x 16 cols at window col 8t)
        u32 G[10][4];
#pragma unroll
        for (int t = 0; t < 10; ++t) ldmx4(G[t], aH + (u32)t * 16);

        // term0: xh * kh
#pragma unroll
        for (int j = 0; j < 8; ++j) {
            mma16816(acc[j], G[j],     bk0.x, bk0.y);
            mma16816(acc[j], G[j + 2], bk1.x, bk1.y);
        }
        // term2: xh * kl
#pragma unroll
        for (int j = 0; j < 8; ++j) {
            mma16816(acc[j], G[j],     bl0.x, bl0.y);
            mma16816(acc[j], G[j + 2], bl1.x, bl1.y);
        }
        // A lo-plane frags, term1: xl * kh
#pragma unroll
        for (int t = 0; t < 10; ++t) ldmx4(G[t], aL + (u32)t * 16);
#pragma unroll
        for (int j = 0; j < 8; ++j) {
            mma16816(acc[j], G[j],     bk0.x, bk0.y);
            mma16816(acc[j], G[j + 2], bk1.x, bk1.y);
        }
    }

    // ---- epilogue: D frag c0,c1 -> (row g, col 2c,2c+1); c2,c3 -> row g+8 ----
    const int r0 = Yb + w * 16 + (lane >> 2);
    const int c0 = Xb + (lane & 3) * 2;
    float* o0 = dout + ((size_t)img * H + r0) * W + c0;
    float* o1 = o0 + 8 * W;
#pragma unroll
    for (int j = 0; j < 8; ++j) {
        *reinterpret_cast<float2*>(o0 + 8 * j) = make_float2(acc[j][0], acc[j][1]);
        *reinterpret_cast<float2*>(o1 + 8 * j) = make_float2(acc[j][2], acc[j][3]);
    }
}

extern "C" void kernel_launch(void* const* d_in, const int* in_sizes, int n_in,
                              void* d_out, int out_size) {
    const float* x = (const float*)d_in[0];   // (32,3,512,512) fp32
    const float* k = (const float*)d_in[1];   // (32,1,21,21)  fp32
    float* out = (float*)d_out;

    cudaFuncSetAttribute(conv_mma, cudaFuncAttributeMaxDynamicSharedMemorySize,
                         SMEM_TOTAL);
    dim3 grid(W / 64, H / 64, 96);            // (8, 8, 96)
    conv_mma<<<grid, 128, SMEM_TOTAL>>>(x, k, out);
}

// round 16
// speedup vs baseline: 2.5431x; 1.5145x over previous
#include <cuda_runtime.h>
#include <cuda_fp16.h>
#include <cstdint>

#define NCHAN 3
#define H 512
#define W 512

// CTA: 64 out rows x 64 out cols, 128 threads = 4 warps (warp w: rows w*16..+15).
// Window: input rows Yb-10..Yb+73 (84), cols Xb-12..Xb+75 (88).
// A plane interleaved fp16: k' = 2c -> xh, 2c+1 -> xl  (176 fp16 = 352B used)
// Row stride 368B = 23 x 16B (odd -> ldmatrix 8-row fetch conflict-free).
#define WR   84
#define WRB  368

#define OFF_AI 0
#define OFF_BF (WR * WRB)                         // 30912
#define SMEM_TOTAL (OFF_BF + 21 * 4 * 32 * 8)     // + 21504 = 52416 B

typedef uint32_t u32;

__device__ __forceinline__ u32 s2u(const void* p) {
    u32 a;
    asm("{ .reg .u64 t; cvta.to.shared.u64 t, %1; cvt.u32.u64 %0, t; }"
        : "=r"(a) : "l"(p));
    return a;
}
__device__ __forceinline__ void mma_f16(float* d, const u32* a, u32 b0, u32 b1) {
    asm volatile("mma.sync.aligned.m16n8k16.row.col.f32.f16.f16.f32 "
        "{%0,%1,%2,%3}, {%4,%5,%6,%7}, {%8,%9}, {%0,%1,%2,%3};"
        : "+f"(d[0]), "+f"(d[1]), "+f"(d[2]), "+f"(d[3])
        : "r"(a[0]), "r"(a[1]), "r"(a[2]), "r"(a[3]), "r"(b0), "r"(b1));
}
__device__ __forceinline__ void ldmx4(u32* g, u32 addr) {
    asm volatile("ldmatrix.sync.aligned.m8n8.x4.shared.b16 {%0,%1,%2,%3}, [%4];"
        : "=r"(g[0]), "=r"(g[1]), "=r"(g[2]), "=r"(g[3]) : "r"(addr));
}
__device__ __forceinline__ unsigned short f2h(float v) {
    return __half_as_ushort(__float2half(v));
}
__device__ __forceinline__ float h2f(unsigned short u) {
    return __half2float(__ushort_as_half(u));
}

__global__ __launch_bounds__(128, 4) void conv_mma(const float* __restrict__ x,
                                                   const float* __restrict__ dk,
                                                   float* __restrict__ dout) {
    extern __shared__ __align__(16) char sm[];
    const u32 smb = s2u(sm);
    const int tid  = threadIdx.x;
    const int w    = tid >> 5;
    const int lane = tid & 31;
    const int img  = blockIdx.z;
    const int Xb   = blockIdx.x * 64;
    const int Yb   = blockIdx.y * 64;

    // ---- B fragments ---------------------------------------------------------
    // Per (dy, s): frag covers frag-k'' in [0,16) of K-segment s; value depends
    // only on dx = 8s + (k''>>1) - n'' - 2 (j-independent). Duplicated parity.
    // col-major B frag: n'' = lane>>2, k0 = (lane&3)*2; b0 = k''{k0,k0+1} (same
    // tap), b1 = k''{k0+8,k0+9} (tap at dx+4).
    const float* kp = dk + (size_t)(img / NCHAN) * 441;
    uint2* Bf = reinterpret_cast<uint2*>(sm + OFF_BF);
    for (int t = 0; t < 21; ++t) {
        int i = tid + (t << 7);            // 21*128 = 2688 entries
        int dy = i >> 7, r = i & 127;
        int s = r >> 5, l2 = r & 31;
        int n2 = l2 >> 2, k0 = (l2 & 3) * 2;
        int dxb = 8 * s + (k0 >> 1) - n2 - 2;
        float t0 = (dxb >= 0 && dxb <= 20) ? kp[dy * 21 + dxb] : 0.f;
        int dx4 = dxb + 4;
        float t1 = (dx4 >= 0 && dx4 <= 20) ? kp[dy * 21 + dx4] : 0.f;
        u32 h0 = f2h(t0), h1 = f2h(t1);
        Bf[(dy * 4 + s) * 32 + l2] = make_uint2(h0 | (h0 << 16), h1 | (h1 << 16));
    }

    // ---- window load: fp32 -> interleaved (xh, xl) fp16 ----------------------
    const float* ximg = x + (size_t)img * H * W;
    for (int i = tid; i < WR * 22; i += 128) {
        int row = i / 22, q = i % 22;
        int gy = Yb - 10 + row, gx = Xb - 12 + 4 * q;
        float4 v = make_float4(0.f, 0.f, 0.f, 0.f);
        if ((unsigned)gy < H && gx >= 0 && gx <= W - 4)
            v = *reinterpret_cast<const float4*>(ximg + (size_t)gy * W + gx);
        unsigned short h0 = f2h(v.x), h1 = f2h(v.y), h2 = f2h(v.z), h3 = f2h(v.w);
        unsigned short l0 = f2h(v.x - h2f(h0)), l1 = f2h(v.y - h2f(h1));
        unsigned short l2 = f2h(v.z - h2f(h2)), l3 = f2h(v.w - h2f(h3));
        // 4 data cols -> 8 interleaved fp16 = 16B
        uint4 pk = make_uint4((u32)h0 | ((u32)l0 << 16), (u32)h1 | ((u32)l1 << 16),
                              (u32)h2 | ((u32)l2 << 16), (u32)h3 | ((u32)l3 << 16));
        *reinterpret_cast<uint4*>(sm + OFF_AI + (u32)row * WRB + (u32)q * 16) = pk;
    }
    __syncthreads();

    // ---- main loop ------------------------------------------------------------
    const u32 lrow = (u32)(lane & 15);
    const u32 lcol = (u32)(lane >> 4) * 16;

    float acc[8][4];
#pragma unroll
    for (int j = 0; j < 8; ++j)
#pragma unroll
        for (int q = 0; q < 4; ++q) acc[j][q] = 0.f;

#pragma unroll 1
    for (int dy = 0; dy < 21; ++dy) {
        const u32 rb = (u32)(w * 16 + dy);
        const u32 aA = smb + OFF_AI + (rb + lrow) * WRB + lcol;

        // 4 B frags serve all j blocks this dy
        uint2 Bs[4];
#pragma unroll
        for (int s = 0; s < 4; ++s) Bs[s] = Bf[(dy * 4 + s) * 32 + lane];

        // 11 A blocks: G[t] = 16 rows x 16 interleaved-k' at byte col 32t
        u32 G[11][4];
#pragma unroll
        for (int t = 0; t < 11; ++t) ldmx4(G[t], aA + (u32)t * 32);

#pragma unroll
        for (int j = 0; j < 8; ++j) {
#pragma unroll
            for (int s = 0; s < 4; ++s)
                mma_f16(acc[j], G[j + s], Bs[s].x, Bs[s].y);
        }
    }

    // ---- epilogue: c0,c1 -> (row g, col 2c,2c+1); c2,c3 -> row g+8 -----------
    const int r0 = Yb + w * 16 + (lane >> 2);
    const int c0 = Xb + (lane & 3) * 2;
    float* o0 = dout + ((size_t)img * H + r0) * W + c0;
    float* o1 = o0 + 8 * W;
#pragma unroll
    for (int j = 0; j < 8; ++j) {
        *reinterpret_cast<float2*>(o0 + 8 * j) = make_float2(acc[j][0], acc[j][1]);
        *reinterpret_cast<float2*>(o1 + 8 * j) = make_float2(acc[j][2], acc[j][3]);
    }
}

extern "C" void kernel_launch(void* const* d_in, const int* in_sizes, int n_in,
                              void* d_out, int out_size) {
    const float* x = (const float*)d_in[0];   // (32,3,512,512) fp32
    const float* k = (const float*)d_in[1];   // (32,1,21,21)  fp32
    float* out = (float*)d_out;

    cudaFuncSetAttribute(conv_mma, cudaFuncAttributeMaxDynamicSharedMemorySize,
                         SMEM_TOTAL);
    dim3 grid(W / 64, H / 64, 96);            // (8, 8, 96)
    conv_mma<<<grid, 128, SMEM_TOTAL>>>(x, k, out);
}